// round 16
// baseline (speedup 1.0000x reference)
#include <cuda_runtime.h>
#include <cuda_fp16.h>
#include <math.h>
#include <stdint.h>

#define NN 8192
#define EE 262144
#define FI 256
#define HH 4
#define CC 32
#define DD 128
#define ETOT (EE + NN)
#define QK_SCALE_LOG2 (0.17677669529663687f * 1.4426950408889634f)
#define LSCALE 64.0f
#define TILES (NN / 32)

// ---------------- scratch ----------------
__device__ float g_xw[NN * DD];
__device__ float g_asrc[NN * HH];
__device__ float g_adst[NN * HH];
__device__ float g_denom[NN * HH];
__device__ float g_acc[NN * DD];
__device__ float g_h[NN * DD];
__device__ float g_q[HH * NN * CC];
__device__ __half g_kh[HH * NN * CC];
__device__ __half g_hT[(size_t)DD * NN];

// ---------------- helpers ----------------
__device__ __forceinline__ uint32_t smem_u32(const void* p) {
    uint32_t a;
    asm("{ .reg .u64 t; cvta.to.shared.u64 t, %1; cvt.u32.u64 %0, t; }" : "=r"(a) : "l"(p));
    return a;
}
__device__ __forceinline__ uint32_t exp2_h2(float c0, float c1) {
    uint32_t p;
    asm("{\n\t.reg .b32 t;\n\tcvt.rn.f16x2.f32 t, %1, %2;\n\t"
        "ex2.approx.f16x2 %0, t;\n\t}" : "=r"(p) : "f"(c1), "f"(c0));
    return p;
}
__device__ __forceinline__ uint32_t h2u(float lo, float hi) {
    __half2 h = __floats2half2_rn(lo, hi);
    return *(uint32_t*)&h;
}
__device__ __forceinline__ uint32_t hfma2(uint32_t a, uint32_t b, uint32_t c) {
    uint32_t d;
    asm("fma.rn.f16x2 %0, %1, %2, %3;" : "=r"(d) : "r"(a), "r"(b), "r"(c));
    return d;
}
__device__ __forceinline__ uint32_t hadd2u(uint32_t a, uint32_t b) {
    __half2 r = __hadd2(*(__half2*)&a, *(__half2*)&b);
    return *(uint32_t*)&r;
}
__device__ __forceinline__ float2 h2f2(uint32_t p) {
    __half2 h = *(__half2*)&p;
    return __half22float2(h);
}
__device__ __forceinline__ void mma_f16(float* d, const uint32_t* a,
                                        uint32_t b0, uint32_t b1) {
    asm volatile(
        "mma.sync.aligned.m16n8k16.row.col.f32.f16.f16.f32 "
        "{%0,%1,%2,%3}, {%4,%5,%6,%7}, {%8,%9}, {%0,%1,%2,%3};\n"
        : "+f"(d[0]), "+f"(d[1]), "+f"(d[2]), "+f"(d[3])
        : "r"(a[0]), "r"(a[1]), "r"(a[2]), "r"(a[3]), "r"(b0), "r"(b1));
}
__device__ __forceinline__ void ldsm_x4(uint32_t& r0, uint32_t& r1, uint32_t& r2,
                                        uint32_t& r3, uint32_t addr) {
    asm volatile("ldmatrix.sync.aligned.m8n8.x4.shared.b16 {%0,%1,%2,%3}, [%4];"
                 : "=r"(r0), "=r"(r1), "=r"(r2), "=r"(r3) : "r"(addr));
}
#define CP_ASYNC16(dst, src) \
    asm volatile("cp.async.cg.shared.global [%0], [%1], 16;" :: "r"(dst), "l"(src))
#define CP_COMMIT asm volatile("cp.async.commit_group;" ::: "memory")
#define CP_WAIT1 asm volatile("cp.async.wait_group 1;" ::: "memory")
#define CP_WAIT0 asm volatile("cp.async.wait_group 0;" ::: "memory")

// ---------------- kernels ----------------
// g_xw = x @ Wgat; epilogue: a_src/a_dst reductions + zero g_acc/g_denom rows
__global__ __launch_bounds__(256) void k_gemm1(const float* __restrict__ x,
                                               const float* __restrict__ W,
                                               const float* __restrict__ att_src,
                                               const float* __restrict__ att_dst) {
    __shared__ float xs[64][33];
    __shared__ float ws[32][128];
    __shared__ float psrc[64][17], pdst[64][17];
    int n0 = blockIdx.x * 64, tid = threadIdx.x;
    int tr = tid >> 4, tc = tid & 15;
    float acc[4][8];
#pragma unroll
    for (int i = 0; i < 4; i++)
#pragma unroll
        for (int j = 0; j < 8; j++) acc[i][j] = 0.0f;
    for (int kc = 0; kc < FI; kc += 32) {
        __syncthreads();
#pragma unroll
        for (int j = 0; j < 8; j++) {
            int idx = tid + j * 256; int k = idx & 31, r = idx >> 5;
            xs[r][k] = x[(n0 + r) * FI + kc + k];
        }
#pragma unroll
        for (int j = 0; j < 16; j++) {
            int idx = tid + j * 256; int c = idx & 127, k = idx >> 7;
            ws[k][c] = W[(kc + k) * DD + c];
        }
        __syncthreads();
#pragma unroll
        for (int k = 0; k < 32; k++) {
            float a[4];
#pragma unroll
            for (int i = 0; i < 4; i++) a[i] = xs[tr * 4 + i][k];
            float4 b0 = *(const float4*)&ws[k][tc * 8];
            float4 b1 = *(const float4*)&ws[k][tc * 8 + 4];
            float b[8] = {b0.x, b0.y, b0.z, b0.w, b1.x, b1.y, b1.z, b1.w};
#pragma unroll
            for (int i = 0; i < 4; i++)
#pragma unroll
                for (int j = 0; j < 8; j++) acc[i][j] = fmaf(a[i], b[j], acc[i][j]);
        }
    }
    float as[8], ad[8];
#pragma unroll
    for (int j = 0; j < 8; j++) { as[j] = att_src[tc * 8 + j]; ad[j] = att_dst[tc * 8 + j]; }
#pragma unroll
    for (int i = 0; i < 4; i++) {
        int n = n0 + tr * 4 + i;
        *(float4*)&g_xw[n * DD + tc * 8]     = make_float4(acc[i][0], acc[i][1], acc[i][2], acc[i][3]);
        *(float4*)&g_xw[n * DD + tc * 8 + 4] = make_float4(acc[i][4], acc[i][5], acc[i][6], acc[i][7]);
        float s = 0.0f, d = 0.0f;
#pragma unroll
        for (int j = 0; j < 8; j++) { s = fmaf(acc[i][j], as[j], s); d = fmaf(acc[i][j], ad[j], d); }
        psrc[tr * 4 + i][tc] = s;
        pdst[tr * 4 + i][tc] = d;
    }
#pragma unroll
    for (int j = 0; j < 8; j++) {
        int idx = tid + j * 256;
        *(float4*)&g_acc[n0 * DD + idx * 4] = make_float4(0.f, 0.f, 0.f, 0.f);
    }
    __syncthreads();
    {
        int r = tid >> 2, h = tid & 3;
        float s = psrc[r][h * 4] + psrc[r][h * 4 + 1] + psrc[r][h * 4 + 2] + psrc[r][h * 4 + 3];
        float d = pdst[r][h * 4] + pdst[r][h * 4 + 1] + pdst[r][h * 4 + 2] + pdst[r][h * 4 + 3];
        g_asrc[(n0 + r) * HH + h] = s;
        g_adst[(n0 + r) * HH + h] = d;
        g_denom[(n0 + r) * HH + h] = 0.0f;
    }
}

// 2 edges per warp; lane owns 8 channels (R12-measured config)
__global__ void k_edgeacc(const int* __restrict__ adj) {
    int gw = (blockIdx.x * blockDim.x + threadIdx.x) >> 5;
    int lane = threadIdx.x & 31;
    int e = gw * 2 + (lane >> 4);
    if (e >= ETOT) return;
    int l8 = lane & 15;
    int s, d;
    if (e < EE) { s = adj[e]; d = adj[EE + e]; } else { s = d = e - EE; }
    float ph[HH];
#pragma unroll
    for (int h = 0; h < HH; h++) {
        float v = g_asrc[s * HH + h] + g_adst[d * HH + h];
        v = (v >= 0.0f) ? v : 0.2f * v;
        ph[h] = __expf(v);
    }
    if (l8 < HH) atomicAdd(&g_denom[d * HH + l8], ph[l8]);
    float p = ph[l8 >> 2];
    float4 x0 = *(const float4*)&g_xw[s * DD + l8 * 8];
    float4 x1 = *(const float4*)&g_xw[s * DD + l8 * 8 + 4];
    asm volatile("red.global.add.v4.f32 [%0], {%1,%2,%3,%4};"
                 :: "l"(&g_acc[d * DD + l8 * 8]),
                    "f"(x0.x * p), "f"(x0.y * p), "f"(x0.z * p), "f"(x0.w * p) : "memory");
    asm volatile("red.global.add.v4.f32 [%0], {%1,%2,%3,%4};"
                 :: "l"(&g_acc[d * DD + l8 * 8 + 4]),
                    "f"(x1.x * p), "f"(x1.y * p), "f"(x1.z * p), "f"(x1.w * p) : "memory");
}

// ---- fused: h = (acc/denom + bias) @ Wpro ; then q/k projections from smem h ----
// Phase A pool: xs[64][33] (8448 B) | ws[32][128] (16384 B)
// Phase B pool: hs[64][132] (33792 B) | wsb[16][128] (8192 B)  -> pool = 41984 B
#define POOL_BYTES 41984
__global__ __launch_bounds__(256) void k_gemm2qk(const float* __restrict__ bias,
                                                 const float* __restrict__ W,
                                                 const float* __restrict__ Wq,
                                                 const float* __restrict__ Wk) {
    __shared__ __align__(16) char pool[POOL_BYTES];
    float (*xs)[33]   = (float(*)[33])pool;
    float (*ws)[128]  = (float(*)[128])(pool + 8448);
    float (*hs)[132]  = (float(*)[132])pool;
    float (*wsb)[128] = (float(*)[128])(pool + 33792);

    int n0 = blockIdx.x * 64, tid = threadIdx.x;
    int tr = tid >> 4, tc = tid & 15;

    // ---------- phase A: h = (acc/denom + bias) @ Wpro ----------
    float acc[4][8];
#pragma unroll
    for (int i = 0; i < 4; i++)
#pragma unroll
        for (int j = 0; j < 8; j++) acc[i][j] = 0.0f;
    for (int kc = 0; kc < DD; kc += 32) {
        __syncthreads();
#pragma unroll
        for (int j = 0; j < 8; j++) {
            int idx = tid + j * 256; int k = idx & 31, r = idx >> 5;
            int n = n0 + r, col = kc + k;
            xs[r][k] = g_acc[n * DD + col] / g_denom[n * HH + (col >> 5)] + bias[col];
        }
#pragma unroll
        for (int j = 0; j < 16; j++) {
            int idx = tid + j * 256; int c = idx & 127, k = idx >> 7;
            ws[k][c] = W[(kc + k) * DD + c];
        }
        __syncthreads();
#pragma unroll
        for (int k = 0; k < 32; k++) {
            float a[4];
#pragma unroll
            for (int i = 0; i < 4; i++) a[i] = xs[tr * 4 + i][k];
            float4 b0 = *(const float4*)&ws[k][tc * 8];
            float4 b1 = *(const float4*)&ws[k][tc * 8 + 4];
            float b[8] = {b0.x, b0.y, b0.z, b0.w, b1.x, b1.y, b1.z, b1.w};
#pragma unroll
            for (int i = 0; i < 4; i++)
#pragma unroll
                for (int j = 0; j < 8; j++) acc[i][j] = fmaf(a[i], b[j], acc[i][j]);
        }
    }
    __syncthreads();   // all reads of xs/ws done before pool is repurposed
    // epilogue: g_h, g_hT(fp16 transpose), hs (smem, for phase B)
#pragma unroll
    for (int i = 0; i < 4; i++) {
        int n = n0 + tr * 4 + i;
        *(float4*)&g_h[n * DD + tc * 8]     = make_float4(acc[i][0], acc[i][1], acc[i][2], acc[i][3]);
        *(float4*)&g_h[n * DD + tc * 8 + 4] = make_float4(acc[i][4], acc[i][5], acc[i][6], acc[i][7]);
        *(float4*)&hs[tr * 4 + i][tc * 8]     = make_float4(acc[i][0], acc[i][1], acc[i][2], acc[i][3]);
        *(float4*)&hs[tr * 4 + i][tc * 8 + 4] = make_float4(acc[i][4], acc[i][5], acc[i][6], acc[i][7]);
    }
#pragma unroll
    for (int j = 0; j < 8; j++) {
        int dcol = tc * 8 + j;
        uint32_t lo = h2u(acc[0][j], acc[1][j]);
        uint32_t hi = h2u(acc[2][j], acc[3][j]);
        *(uint2*)(g_hT + (size_t)dcol * NN + n0 + tr * 4) = make_uint2(lo, hi);
    }

    // ---------- phase B: q/k projections ----------
#pragma unroll
    for (int half = 0; half < 2; half++) {
        const float* W2 = half ? Wk : Wq;
        float accb[4][8];
#pragma unroll
        for (int i = 0; i < 4; i++)
#pragma unroll
            for (int j = 0; j < 8; j++) accb[i][j] = 0.0f;
        for (int kc = 0; kc < DD; kc += 16) {
            __syncthreads();
#pragma unroll
            for (int j = 0; j < 8; j++) {
                int idx = tid + j * 256; int c = idx & 127, k = idx >> 7;
                wsb[k][c] = W2[((c >> 5) * DD + kc + k) * CC + (c & 31)];
            }
            __syncthreads();
#pragma unroll
            for (int k = 0; k < 16; k++) {
                float a[4];
#pragma unroll
                for (int i = 0; i < 4; i++) a[i] = hs[tr * 4 + i][kc + k];
#pragma unroll
                for (int j = 0; j < 8; j++) {
                    float b = wsb[k][tc + j * 16];   // conflict-free broadcast
#pragma unroll
                    for (int i = 0; i < 4; i++) accb[i][j] = fmaf(a[i], b, accb[i][j]);
                }
            }
        }
#pragma unroll
        for (int i = 0; i < 4; i++) {
            int n = n0 + tr * 4 + i;
#pragma unroll
            for (int j = 0; j < 8; j++) {
                int cg = tc + j * 16;
                int h = cg >> 5, c = cg & 31;
                if (half == 0)
                    g_q[((size_t)h * NN + n) * CC + c] = accb[i][j] * QK_SCALE_LOG2;
                else
                    g_kh[((size_t)h * NN + n) * CC + c] = __float2half(accb[i][j]);
            }
        }
    }
}

// ---- fused two-phase attention + residual + layernorm ----
// grid NN/64, 128 thr (4 warps x 16 rows); writes final output.
__global__ __launch_bounds__(128) void k_attnF(const float* __restrict__ lng,
                                               const float* __restrict__ lnb,
                                               float* __restrict__ out) {
    __shared__ __half Ks[2][HH][32][40];
    __shared__ __half Vs[2][128][40];
    __shared__ float sg[DD], sb[DD];

    const int tid = threadIdx.x;
    const int w = tid >> 5, lane = tid & 31;
    const int qb = blockIdx.x * 64;
    const int lr = lane >> 2, lc = lane & 3;
    const int row0 = qb + w * 16 + lr;

    if (tid < DD) { sg[tid] = lng[tid]; sb[tid] = lnb[tid]; }

    uint32_t qa[HH][2][4];
#pragma unroll
    for (int h = 0; h < HH; h++) {
        const float* q0 = g_q + ((size_t)h * NN + row0) * CC;
        const float* q1 = q0 + 8 * CC;
#pragma unroll
        for (int c = 0; c < 2; c++) {
            int k0 = c * 16 + 2 * lc;
            qa[h][c][0] = h2u(q0[k0], q0[k0 + 1]);
            qa[h][c][1] = h2u(q1[k0], q1[k0 + 1]);
            qa[h][c][2] = h2u(q0[k0 + 8], q0[k0 + 9]);
            qa[h][c][3] = h2u(q1[k0 + 8], q1[k0 + 9]);
        }
    }

    uint32_t kbase = smem_u32(&Ks[0][0][lane & 7][(lane >> 3) * 8]);
    uint32_t vbase = smem_u32(&Vs[0][((lane >> 4) * 8) + (lane & 7)][((lane >> 3) & 1) * 8]);

    auto load_k = [&](int kt, int buf) {
#pragma unroll
        for (int i = 0; i < 4; i++) {
            int idx = tid + i * 128;
            int h = idx >> 7, row = (idx >> 2) & 31, chunk = idx & 3;
            CP_ASYNC16(smem_u32(&Ks[buf][h][row][chunk * 8]),
                       g_kh + ((size_t)h * NN + kt * 32 + row) * CC + chunk * 8);
        }
    };
    auto load_v = [&](int kt, int buf) {
#pragma unroll
        for (int i = 0; i < 4; i++) {
            int idx = tid + i * 128;
            int row = idx >> 2, chunk = idx & 3;
            CP_ASYNC16(smem_u32(&Vs[buf][row][chunk * 8]),
                       g_hT + (size_t)row * NN + kt * 32 + chunk * 8);
        }
    };

    // ---------- phase 1: l per head ----------
    float lsum[HH][2];
#pragma unroll
    for (int h = 0; h < HH; h++) lsum[h][0] = lsum[h][1] = 0.0f;

    load_k(0, 0);
    CP_COMMIT;
    for (int kb = 0; kb < TILES; kb++) {
        int buf = kb & 1;
        if (kb + 1 < TILES) { load_k(kb + 1, buf ^ 1); CP_COMMIT; CP_WAIT1; }
        else CP_WAIT0;
        __syncthreads();
#pragma unroll
        for (int h = 0; h < HH; h++) {
            float ef[4][4];
            uint32_t e0[4], e1[4];
#pragma unroll
            for (int j = 0; j < 4; j++) {
#pragma unroll
                for (int i = 0; i < 4; i++) ef[j][i] = 0.0f;
                uint32_t k0, k1, k2, k3;
                ldsm_x4(k0, k1, k2, k3, kbase + buf * 10240 + h * 2560 + j * 640);
                mma_f16(ef[j], qa[h][0], k0, k1);
                mma_f16(ef[j], qa[h][1], k2, k3);
                e0[j] = exp2_h2(ef[j][0], ef[j][1]);
                e1[j] = exp2_h2(ef[j][2], ef[j][3]);
            }
            float2 f0 = h2f2(hadd2u(hadd2u(e0[0], e0[1]), hadd2u(e0[2], e0[3])));
            float2 f1 = h2f2(hadd2u(hadd2u(e1[0], e1[1]), hadd2u(e1[2], e1[3])));
            lsum[h][0] += f0.x + f0.y;
            lsum[h][1] += f1.x + f1.y;
        }
        __syncthreads();
    }
    uint32_t ihh[HH][2];
#pragma unroll
    for (int h = 0; h < HH; h++) {
#pragma unroll
        for (int r = 0; r < 2; r++) {
            lsum[h][r] += __shfl_xor_sync(0xffffffffu, lsum[h][r], 1);
            lsum[h][r] += __shfl_xor_sync(0xffffffffu, lsum[h][r], 2);
        }
        float il0 = LSCALE / lsum[h][0];
        float il1 = LSCALE / lsum[h][1];
        ihh[h][0] = h2u(il0, il0);
        ihh[h][1] = h2u(il1, il1);
    }

    // ---------- phase 2 ----------
    float of[16][4];
#pragma unroll
    for (int j = 0; j < 16; j++)
#pragma unroll
        for (int i = 0; i < 4; i++) of[j][i] = 0.0f;

    __syncthreads();
    load_k(0, 0);
    load_v(0, 0);
    CP_COMMIT;
    for (int kb = 0; kb < TILES; kb++) {
        int buf = kb & 1;
        if (kb + 1 < TILES) { load_k(kb + 1, buf ^ 1); load_v(kb + 1, buf ^ 1); CP_COMMIT; CP_WAIT1; }
        else CP_WAIT0;
        __syncthreads();

        uint32_t pa[2][4];
#pragma unroll
        for (int t = 0; t < 2; t++)
#pragma unroll
            for (int i = 0; i < 4; i++) pa[t][i] = 0u;

#pragma unroll
        for (int h = 0; h < HH; h++) {
            float ef[4][4];
#pragma unroll
            for (int j = 0; j < 4; j++) {
#pragma unroll
                for (int i = 0; i < 4; i++) ef[j][i] = 0.0f;
                uint32_t k0, k1, k2, k3;
                ldsm_x4(k0, k1, k2, k3, kbase + buf * 10240 + h * 2560 + j * 640);
                mma_f16(ef[j], qa[h][0], k0, k1);
                mma_f16(ef[j], qa[h][1], k2, k3);
            }
#pragma unroll
            for (int t = 0; t < 2; t++) {
                pa[t][0] = hfma2(exp2_h2(ef[2 * t][0], ef[2 * t][1]), ihh[h][0], pa[t][0]);
                pa[t][1] = hfma2(exp2_h2(ef[2 * t][2], ef[2 * t][3]), ihh[h][1], pa[t][1]);
                pa[t][2] = hfma2(exp2_h2(ef[2 * t + 1][0], ef[2 * t + 1][1]), ihh[h][0], pa[t][2]);
                pa[t][3] = hfma2(exp2_h2(ef[2 * t + 1][2], ef[2 * t + 1][3]), ihh[h][1], pa[t][3]);
            }
        }
#pragma unroll
        for (int t = 0; t < 2; t++) {
#pragma unroll
            for (int jp = 0; jp < 8; jp++) {
                uint32_t v0, v1, v2, v3;
                ldsm_x4(v0, v1, v2, v3, vbase + buf * 10240 + jp * 1280 + t * 32);
                mma_f16(of[2 * jp],     pa[t], v0, v1);
                mma_f16(of[2 * jp + 1], pa[t], v2, v3);
            }
        }
        __syncthreads();
    }

    // ---------- epilogue: residual + layernorm, write final out ----------
    const float s = 1.0f / LSCALE;
#pragma unroll
    for (int m = 0; m < 2; m++) {
        int row = row0 + m * 8;
        float sum = 0.0f, sum2 = 0.0f;
#pragma unroll
        for (int j = 0; j < 16; j++) {
            int col = j * 8 + lc * 2;
            float2 hv = *(const float2*)&g_h[(size_t)row * DD + col];
            float y0 = fmaf(of[j][2 * m],     s, hv.x);
            float y1 = fmaf(of[j][2 * m + 1], s, hv.y);
            sum += y0 + y1;
            sum2 += y0 * y0 + y1 * y1;
        }
        sum  += __shfl_xor_sync(0xffffffffu, sum, 1);
        sum  += __shfl_xor_sync(0xffffffffu, sum, 2);
        sum2 += __shfl_xor_sync(0xffffffffu, sum2, 1);
        sum2 += __shfl_xor_sync(0xffffffffu, sum2, 2);
        float mu = sum * (1.0f / DD);
        float var = sum2 * (1.0f / DD) - mu * mu;
        float rstd = rsqrtf(var + 1e-5f);
#pragma unroll
        for (int j = 0; j < 16; j++) {
            int col = j * 8 + lc * 2;
            float2 hv = *(const float2*)&g_h[(size_t)row * DD + col];
            float y0 = fmaf(of[j][2 * m],     s, hv.x);
            float y1 = fmaf(of[j][2 * m + 1], s, hv.y);
            float2 o;
            o.x = (y0 - mu) * rstd * sg[col]     + sb[col];
            o.y = (y1 - mu) * rstd * sg[col + 1] + sb[col + 1];
            *(float2*)&out[(size_t)row * DD + col] = o;
        }
    }
}

// ---------------- launch ----------------
extern "C" void kernel_launch(void* const* d_in, const int* in_sizes, int n_in,
                              void* d_out, int out_size) {
    const float* x        = (const float*)d_in[0];
    const int*   adj      = (const int*)d_in[1];
    const float* Wgat     = (const float*)d_in[2];
    const float* att_src  = (const float*)d_in[3];
    const float* att_dst  = (const float*)d_in[4];
    const float* bias_gat = (const float*)d_in[5];
    const float* Wq       = (const float*)d_in[6];
    const float* Wk       = (const float*)d_in[7];
    const float* Wpro     = (const float*)d_in[8];
    const float* lng      = (const float*)d_in[9];
    const float* lnb      = (const float*)d_in[10];
    float* out = (float*)d_out;

    k_gemm1<<<NN / 64, 256>>>(x, Wgat, att_src, att_dst);
    {
        int warps = (ETOT + 1) / 2;
        k_edgeacc<<<(warps * 32 + 255) / 256, 256>>>(adj);
    }
    k_gemm2qk<<<NN / 64, 256>>>(bias_gat, Wpro, Wq, Wk);
    k_attnF<<<NN / 64, 128>>>(lng, lnb, out);
}

// round 17
// speedup vs baseline: 1.0373x; 1.0373x over previous
#include <cuda_runtime.h>
#include <cuda_fp16.h>
#include <math.h>
#include <stdint.h>

#define NN 8192
#define EE 262144
#define FI 256
#define HH 4
#define CC 32
#define DD 128
#define ETOT (EE + NN)
#define QK_SCALE_LOG2 (0.17677669529663687f * 1.4426950408889634f)
#define LSCALE 64.0f
#define TILES (NN / 32)
#define HALF_TILES (TILES / 2)

// ---------------- scratch ----------------
__device__ float g_xw[NN * DD];
__device__ float g_asrc[NN * HH];
__device__ float g_adst[NN * HH];
__device__ float g_denom[NN * HH];
__device__ float g_acc[NN * DD];
__device__ float g_h[NN * DD];
__device__ float g_q[HH * NN * CC];
__device__ __half g_kh[HH * NN * CC];
__device__ __half g_hT[(size_t)DD * NN];

// ---------------- helpers ----------------
__device__ __forceinline__ uint32_t smem_u32(const void* p) {
    uint32_t a;
    asm("{ .reg .u64 t; cvta.to.shared.u64 t, %1; cvt.u32.u64 %0, t; }" : "=r"(a) : "l"(p));
    return a;
}
__device__ __forceinline__ uint32_t exp2_h2(float c0, float c1) {
    uint32_t p;
    asm("{\n\t.reg .b32 t;\n\tcvt.rn.f16x2.f32 t, %1, %2;\n\t"
        "ex2.approx.f16x2 %0, t;\n\t}" : "=r"(p) : "f"(c1), "f"(c0));
    return p;
}
__device__ __forceinline__ uint32_t h2u(float lo, float hi) {
    __half2 h = __floats2half2_rn(lo, hi);
    return *(uint32_t*)&h;
}
__device__ __forceinline__ uint32_t hfma2(uint32_t a, uint32_t b, uint32_t c) {
    uint32_t d;
    asm("fma.rn.f16x2 %0, %1, %2, %3;" : "=r"(d) : "r"(a), "r"(b), "r"(c));
    return d;
}
__device__ __forceinline__ uint32_t hadd2u(uint32_t a, uint32_t b) {
    __half2 r = __hadd2(*(__half2*)&a, *(__half2*)&b);
    return *(uint32_t*)&r;
}
__device__ __forceinline__ float2 h2f2(uint32_t p) {
    __half2 h = *(__half2*)&p;
    return __half22float2(h);
}
__device__ __forceinline__ void mma_f16(float* d, const uint32_t* a,
                                        uint32_t b0, uint32_t b1) {
    asm volatile(
        "mma.sync.aligned.m16n8k16.row.col.f32.f16.f16.f32 "
        "{%0,%1,%2,%3}, {%4,%5,%6,%7}, {%8,%9}, {%0,%1,%2,%3};\n"
        : "+f"(d[0]), "+f"(d[1]), "+f"(d[2]), "+f"(d[3])
        : "r"(a[0]), "r"(a[1]), "r"(a[2]), "r"(a[3]), "r"(b0), "r"(b1));
}
__device__ __forceinline__ void ldsm_x4(uint32_t& r0, uint32_t& r1, uint32_t& r2,
                                        uint32_t& r3, uint32_t addr) {
    asm volatile("ldmatrix.sync.aligned.m8n8.x4.shared.b16 {%0,%1,%2,%3}, [%4];"
                 : "=r"(r0), "=r"(r1), "=r"(r2), "=r"(r3) : "r"(addr));
}
#define CP_ASYNC16(dst, src) \
    asm volatile("cp.async.cg.shared.global [%0], [%1], 16;" :: "r"(dst), "l"(src))
#define CP_COMMIT asm volatile("cp.async.commit_group;" ::: "memory")
#define CP_WAIT0 asm volatile("cp.async.wait_group 0;" ::: "memory")
#define BARG(gid) asm volatile("bar.sync %0, 128;" :: "r"((gid) + 1) : "memory")

// ---------------- kernels ----------------
// g_xw = x @ Wgat; epilogue: a_src/a_dst reductions + zero g_acc/g_denom rows
__global__ __launch_bounds__(256) void k_gemm1(const float* __restrict__ x,
                                               const float* __restrict__ W,
                                               const float* __restrict__ att_src,
                                               const float* __restrict__ att_dst) {
    __shared__ float xs[64][33];
    __shared__ float ws[32][128];
    __shared__ float psrc[64][17], pdst[64][17];
    int n0 = blockIdx.x * 64, tid = threadIdx.x;
    int tr = tid >> 4, tc = tid & 15;
    float acc[4][8];
#pragma unroll
    for (int i = 0; i < 4; i++)
#pragma unroll
        for (int j = 0; j < 8; j++) acc[i][j] = 0.0f;
    for (int kc = 0; kc < FI; kc += 32) {
        __syncthreads();
#pragma unroll
        for (int j = 0; j < 8; j++) {
            int idx = tid + j * 256; int k = idx & 31, r = idx >> 5;
            xs[r][k] = x[(n0 + r) * FI + kc + k];
        }
#pragma unroll
        for (int j = 0; j < 16; j++) {
            int idx = tid + j * 256; int c = idx & 127, k = idx >> 7;
            ws[k][c] = W[(kc + k) * DD + c];
        }
        __syncthreads();
#pragma unroll
        for (int k = 0; k < 32; k++) {
            float a[4];
#pragma unroll
            for (int i = 0; i < 4; i++) a[i] = xs[tr * 4 + i][k];
            float4 b0 = *(const float4*)&ws[k][tc * 8];
            float4 b1 = *(const float4*)&ws[k][tc * 8 + 4];
            float b[8] = {b0.x, b0.y, b0.z, b0.w, b1.x, b1.y, b1.z, b1.w};
#pragma unroll
            for (int i = 0; i < 4; i++)
#pragma unroll
                for (int j = 0; j < 8; j++) acc[i][j] = fmaf(a[i], b[j], acc[i][j]);
        }
    }
    float as[8], ad[8];
#pragma unroll
    for (int j = 0; j < 8; j++) { as[j] = att_src[tc * 8 + j]; ad[j] = att_dst[tc * 8 + j]; }
#pragma unroll
    for (int i = 0; i < 4; i++) {
        int n = n0 + tr * 4 + i;
        *(float4*)&g_xw[n * DD + tc * 8]     = make_float4(acc[i][0], acc[i][1], acc[i][2], acc[i][3]);
        *(float4*)&g_xw[n * DD + tc * 8 + 4] = make_float4(acc[i][4], acc[i][5], acc[i][6], acc[i][7]);
        float s = 0.0f, d = 0.0f;
#pragma unroll
        for (int j = 0; j < 8; j++) { s = fmaf(acc[i][j], as[j], s); d = fmaf(acc[i][j], ad[j], d); }
        psrc[tr * 4 + i][tc] = s;
        pdst[tr * 4 + i][tc] = d;
    }
#pragma unroll
    for (int j = 0; j < 8; j++) {
        int idx = tid + j * 256;
        *(float4*)&g_acc[n0 * DD + idx * 4] = make_float4(0.f, 0.f, 0.f, 0.f);
    }
    __syncthreads();
    {
        int r = tid >> 2, h = tid & 3;
        float s = psrc[r][h * 4] + psrc[r][h * 4 + 1] + psrc[r][h * 4 + 2] + psrc[r][h * 4 + 3];
        float d = pdst[r][h * 4] + pdst[r][h * 4 + 1] + pdst[r][h * 4 + 2] + pdst[r][h * 4 + 3];
        g_asrc[(n0 + r) * HH + h] = s;
        g_adst[(n0 + r) * HH + h] = d;
        g_denom[(n0 + r) * HH + h] = 0.0f;
    }
}

// 2 edges per warp; lane owns 8 channels
__global__ void k_edgeacc(const int* __restrict__ adj) {
    int gw = (blockIdx.x * blockDim.x + threadIdx.x) >> 5;
    int lane = threadIdx.x & 31;
    int e = gw * 2 + (lane >> 4);
    if (e >= ETOT) return;
    int l8 = lane & 15;
    int s, d;
    if (e < EE) { s = adj[e]; d = adj[EE + e]; } else { s = d = e - EE; }
    float ph[HH];
#pragma unroll
    for (int h = 0; h < HH; h++) {
        float v = g_asrc[s * HH + h] + g_adst[d * HH + h];
        v = (v >= 0.0f) ? v : 0.2f * v;
        ph[h] = __expf(v);
    }
    if (l8 < HH) atomicAdd(&g_denom[d * HH + l8], ph[l8]);
    float p = ph[l8 >> 2];
    float4 x0 = *(const float4*)&g_xw[s * DD + l8 * 8];
    float4 x1 = *(const float4*)&g_xw[s * DD + l8 * 8 + 4];
    asm volatile("red.global.add.v4.f32 [%0], {%1,%2,%3,%4};"
                 :: "l"(&g_acc[d * DD + l8 * 8]),
                    "f"(x0.x * p), "f"(x0.y * p), "f"(x0.z * p), "f"(x0.w * p) : "memory");
    asm volatile("red.global.add.v4.f32 [%0], {%1,%2,%3,%4};"
                 :: "l"(&g_acc[d * DD + l8 * 8 + 4]),
                    "f"(x1.x * p), "f"(x1.y * p), "f"(x1.z * p), "f"(x1.w * p) : "memory");
}

// ---- fused: h = (acc/denom + bias) @ Wpro ; then q/k projections from smem h ----
#define POOL_BYTES 41984
__global__ __launch_bounds__(256) void k_gemm2qk(const float* __restrict__ bias,
                                                 const float* __restrict__ W,
                                                 const float* __restrict__ Wq,
                                                 const float* __restrict__ Wk) {
    __shared__ __align__(16) char pool[POOL_BYTES];
    float (*xs)[33]   = (float(*)[33])pool;
    float (*ws)[128]  = (float(*)[128])(pool + 8448);
    float (*hs)[132]  = (float(*)[132])pool;
    float (*wsb)[128] = (float(*)[128])(pool + 33792);

    int n0 = blockIdx.x * 64, tid = threadIdx.x;
    int tr = tid >> 4, tc = tid & 15;

    float acc[4][8];
#pragma unroll
    for (int i = 0; i < 4; i++)
#pragma unroll
        for (int j = 0; j < 8; j++) acc[i][j] = 0.0f;
    for (int kc = 0; kc < DD; kc += 32) {
        __syncthreads();
#pragma unroll
        for (int j = 0; j < 8; j++) {
            int idx = tid + j * 256; int k = idx & 31, r = idx >> 5;
            int n = n0 + r, col = kc + k;
            xs[r][k] = g_acc[n * DD + col] / g_denom[n * HH + (col >> 5)] + bias[col];
        }
#pragma unroll
        for (int j = 0; j < 16; j++) {
            int idx = tid + j * 256; int c = idx & 127, k = idx >> 7;
            ws[k][c] = W[(kc + k) * DD + c];
        }
        __syncthreads();
#pragma unroll
        for (int k = 0; k < 32; k++) {
            float a[4];
#pragma unroll
            for (int i = 0; i < 4; i++) a[i] = xs[tr * 4 + i][k];
            float4 b0 = *(const float4*)&ws[k][tc * 8];
            float4 b1 = *(const float4*)&ws[k][tc * 8 + 4];
            float b[8] = {b0.x, b0.y, b0.z, b0.w, b1.x, b1.y, b1.z, b1.w};
#pragma unroll
            for (int i = 0; i < 4; i++)
#pragma unroll
                for (int j = 0; j < 8; j++) acc[i][j] = fmaf(a[i], b[j], acc[i][j]);
        }
    }
    __syncthreads();
#pragma unroll
    for (int i = 0; i < 4; i++) {
        int n = n0 + tr * 4 + i;
        *(float4*)&g_h[n * DD + tc * 8]     = make_float4(acc[i][0], acc[i][1], acc[i][2], acc[i][3]);
        *(float4*)&g_h[n * DD + tc * 8 + 4] = make_float4(acc[i][4], acc[i][5], acc[i][6], acc[i][7]);
        *(float4*)&hs[tr * 4 + i][tc * 8]     = make_float4(acc[i][0], acc[i][1], acc[i][2], acc[i][3]);
        *(float4*)&hs[tr * 4 + i][tc * 8 + 4] = make_float4(acc[i][4], acc[i][5], acc[i][6], acc[i][7]);
    }
#pragma unroll
    for (int j = 0; j < 8; j++) {
        int dcol = tc * 8 + j;
        uint32_t lo = h2u(acc[0][j], acc[1][j]);
        uint32_t hi = h2u(acc[2][j], acc[3][j]);
        *(uint2*)(g_hT + (size_t)dcol * NN + n0 + tr * 4) = make_uint2(lo, hi);
    }

#pragma unroll
    for (int half = 0; half < 2; half++) {
        const float* W2 = half ? Wk : Wq;
        float accb[4][8];
#pragma unroll
        for (int i = 0; i < 4; i++)
#pragma unroll
            for (int j = 0; j < 8; j++) accb[i][j] = 0.0f;
        for (int kc = 0; kc < DD; kc += 16) {
            __syncthreads();
#pragma unroll
            for (int j = 0; j < 8; j++) {
                int idx = tid + j * 256; int c = idx & 127, k = idx >> 7;
                wsb[k][c] = W2[((c >> 5) * DD + kc + k) * CC + (c & 31)];
            }
            __syncthreads();
#pragma unroll
            for (int k = 0; k < 16; k++) {
                float a[4];
#pragma unroll
                for (int i = 0; i < 4; i++) a[i] = hs[tr * 4 + i][kc + k];
#pragma unroll
                for (int j = 0; j < 8; j++) {
                    float b = wsb[k][tc + j * 16];
#pragma unroll
                    for (int i = 0; i < 4; i++) accb[i][j] = fmaf(a[i], b, accb[i][j]);
                }
            }
        }
#pragma unroll
        for (int i = 0; i < 4; i++) {
            int n = n0 + tr * 4 + i;
#pragma unroll
            for (int j = 0; j < 8; j++) {
                int cg = tc + j * 16;
                int h = cg >> 5, c = cg & 31;
                if (half == 0)
                    g_q[((size_t)h * NN + n) * CC + c] = accb[i][j] * QK_SCALE_LOG2;
                else
                    g_kh[((size_t)h * NN + n) * CC + c] = __float2half(accb[i][j]);
            }
        }
    }
}

// ---- attention: 256 thr = 2 key-split groups of 4 warps; + residual + LN ----
// pool layout: K group g at g*10240 (4 heads x 32 x 40 halves);
//              V group g at 20480 + g*10240 (128 x 40 halves).
__global__ __launch_bounds__(256) void k_attnF(const float* __restrict__ lng,
                                               const float* __restrict__ lnb,
                                               float* __restrict__ out) {
    __shared__ __align__(16) char pool[40960];
    __shared__ float l2[2][HH][64];
    __shared__ float sg[DD], sb[DD];

    const int tid = threadIdx.x;
    const int g = tid >> 7;          // key-split group 0/1
    const int lt = tid & 127;        // local tid within group
    const int wl = lt >> 5;          // local warp 0..3
    const int lane = tid & 31;
    const int qb = blockIdx.x * 64;
    const int lr = lane >> 2, lc = lane & 3;
    const int row0 = qb + wl * 16 + lr;

    if (tid < DD) { sg[tid] = lng[tid]; sb[tid] = lnb[tid]; }

    // Q fragments (duplicated across groups)
    uint32_t qa[HH][2][4];
#pragma unroll
    for (int h = 0; h < HH; h++) {
        const float* q0 = g_q + ((size_t)h * NN + row0) * CC;
        const float* q1 = q0 + 8 * CC;
#pragma unroll
        for (int c = 0; c < 2; c++) {
            int k0 = c * 16 + 2 * lc;
            qa[h][c][0] = h2u(q0[k0], q0[k0 + 1]);
            qa[h][c][1] = h2u(q1[k0], q1[k0 + 1]);
            qa[h][c][2] = h2u(q0[k0 + 8], q0[k0 + 9]);
            qa[h][c][3] = h2u(q1[k0 + 8], q1[k0 + 9]);
        }
    }

    const uint32_t poolb = smem_u32(pool);
    const uint32_t koff = poolb + g * 10240u;
    const uint32_t voff = poolb + 20480u + g * 10240u;
    const uint32_t kbase = koff + (lane & 7) * 80 + (lane >> 3) * 16;
    const uint32_t vbase = voff + (((lane >> 4) * 8) + (lane & 7)) * 80 + ((lane >> 3) & 1) * 16;

    auto load_k = [&](int kt) {
#pragma unroll
        for (int i = 0; i < 4; i++) {
            int idx = lt + i * 128;
            int h = idx >> 7, row = (idx >> 2) & 31, chunk = idx & 3;
            CP_ASYNC16(koff + h * 2560 + row * 80 + chunk * 16,
                       g_kh + ((size_t)h * NN + kt * 32 + row) * CC + chunk * 8);
        }
    };
    auto load_v = [&](int kt) {
#pragma unroll
        for (int i = 0; i < 4; i++) {
            int idx = lt + i * 128;
            int row = idx >> 2, chunk = idx & 3;
            CP_ASYNC16(voff + row * 80 + chunk * 16,
                       g_hT + (size_t)row * NN + kt * 32 + chunk * 8);
        }
    };

    const int kt0 = g * HALF_TILES;

    // ---------- phase 1: group-partial l ----------
    float lsum[HH][2];
#pragma unroll
    for (int h = 0; h < HH; h++) lsum[h][0] = lsum[h][1] = 0.0f;

    for (int kb = 0; kb < HALF_TILES; kb++) {
        BARG(g);                   // group's reads of previous tile done
        load_k(kt0 + kb);
        CP_COMMIT; CP_WAIT0;
        BARG(g);                   // group's loads visible
#pragma unroll
        for (int h = 0; h < HH; h++) {
            float ef[4][4];
            uint32_t e0[4], e1[4];
#pragma unroll
            for (int j = 0; j < 4; j++) {
#pragma unroll
                for (int i = 0; i < 4; i++) ef[j][i] = 0.0f;
                uint32_t k0, k1, k2, k3;
                ldsm_x4(k0, k1, k2, k3, kbase + h * 2560 + j * 640);
                mma_f16(ef[j], qa[h][0], k0, k1);
                mma_f16(ef[j], qa[h][1], k2, k3);
                e0[j] = exp2_h2(ef[j][0], ef[j][1]);
                e1[j] = exp2_h2(ef[j][2], ef[j][3]);
            }
            float2 f0 = h2f2(hadd2u(hadd2u(e0[0], e0[1]), hadd2u(e0[2], e0[3])));
            float2 f1 = h2f2(hadd2u(hadd2u(e1[0], e1[1]), hadd2u(e1[2], e1[3])));
            lsum[h][0] += f0.x + f0.y;
            lsum[h][1] += f1.x + f1.y;
        }
    }
    // quad-reduce, publish group partial, combine
#pragma unroll
    for (int h = 0; h < HH; h++) {
#pragma unroll
        for (int r = 0; r < 2; r++) {
            lsum[h][r] += __shfl_xor_sync(0xffffffffu, lsum[h][r], 1);
            lsum[h][r] += __shfl_xor_sync(0xffffffffu, lsum[h][r], 2);
        }
    }
    if (lc == 0) {
#pragma unroll
        for (int h = 0; h < HH; h++) {
            l2[g][h][wl * 16 + lr]     = lsum[h][0];
            l2[g][h][wl * 16 + lr + 8] = lsum[h][1];
        }
    }
    __syncthreads();
    uint32_t ihh[HH][2];
#pragma unroll
    for (int h = 0; h < HH; h++) {
        float t0 = lsum[h][0] + l2[g ^ 1][h][wl * 16 + lr];
        float t1 = lsum[h][1] + l2[g ^ 1][h][wl * 16 + lr + 8];
        float il0 = LSCALE / t0, il1 = LSCALE / t1;
        ihh[h][0] = h2u(il0, il0);
        ihh[h][1] = h2u(il1, il1);
    }

    // ---------- phase 2: group-partial O ----------
    float of[16][4];
#pragma unroll
    for (int j = 0; j < 16; j++)
#pragma unroll
        for (int i = 0; i < 4; i++) of[j][i] = 0.0f;

    for (int kb = 0; kb < HALF_TILES; kb++) {
        BARG(g);
        load_k(kt0 + kb);
        load_v(kt0 + kb);
        CP_COMMIT; CP_WAIT0;
        BARG(g);

        uint32_t pa[2][4];
#pragma unroll
        for (int t = 0; t < 2; t++)
#pragma unroll
            for (int i = 0; i < 4; i++) pa[t][i] = 0u;

#pragma unroll
        for (int h = 0; h < HH; h++) {
            float ef[4][4];
#pragma unroll
            for (int j = 0; j < 4; j++) {
#pragma unroll
                for (int i = 0; i < 4; i++) ef[j][i] = 0.0f;
                uint32_t k0, k1, k2, k3;
                ldsm_x4(k0, k1, k2, k3, kbase + h * 2560 + j * 640);
                mma_f16(ef[j], qa[h][0], k0, k1);
                mma_f16(ef[j], qa[h][1], k2, k3);
            }
#pragma unroll
            for (int t = 0; t < 2; t++) {
                pa[t][0] = hfma2(exp2_h2(ef[2 * t][0], ef[2 * t][1]), ihh[h][0], pa[t][0]);
                pa[t][1] = hfma2(exp2_h2(ef[2 * t][2], ef[2 * t][3]), ihh[h][1], pa[t][1]);
                pa[t][2] = hfma2(exp2_h2(ef[2 * t + 1][0], ef[2 * t + 1][1]), ihh[h][0], pa[t][2]);
                pa[t][3] = hfma2(exp2_h2(ef[2 * t + 1][2], ef[2 * t + 1][3]), ihh[h][1], pa[t][3]);
            }
        }
#pragma unroll
        for (int t = 0; t < 2; t++) {
#pragma unroll
            for (int jp = 0; jp < 8; jp++) {
                uint32_t v0, v1, v2, v3;
                ldsm_x4(v0, v1, v2, v3, vbase + jp * 1280 + t * 32);
                mma_f16(of[2 * jp],     pa[t], v0, v1);
                mma_f16(of[2 * jp + 1], pa[t], v2, v3);
            }
        }
    }
    __syncthreads();   // all compute done; pool reusable as staging

    // ---------- combine group partials + residual + LN ----------
    float* stg = (float*)pool;
    if (g == 1) {
#pragma unroll
        for (int j = 0; j < 16; j++)
            *(float4*)&stg[j * 512 + lt * 4] =
                make_float4(of[j][0], of[j][1], of[j][2], of[j][3]);
    }
    __syncthreads();
    if (g == 0) {
#pragma unroll
        for (int j = 0; j < 16; j++) {
            float4 v = *(const float4*)&stg[j * 512 + lt * 4];
            of[j][0] += v.x; of[j][1] += v.y; of[j][2] += v.z; of[j][3] += v.w;
        }
        const float s = 1.0f / LSCALE;
#pragma unroll
        for (int m = 0; m < 2; m++) {
            int row = row0 + m * 8;
            float sum = 0.0f, sum2 = 0.0f;
#pragma unroll
            for (int j = 0; j < 16; j++) {
                int col = j * 8 + lc * 2;
                float2 hv = *(const float2*)&g_h[(size_t)row * DD + col];
                float y0 = fmaf(of[j][2 * m],     s, hv.x);
                float y1 = fmaf(of[j][2 * m + 1], s, hv.y);
                sum += y0 + y1;
                sum2 += y0 * y0 + y1 * y1;
            }
            sum  += __shfl_xor_sync(0xffffffffu, sum, 1);
            sum  += __shfl_xor_sync(0xffffffffu, sum, 2);
            sum2 += __shfl_xor_sync(0xffffffffu, sum2, 1);
            sum2 += __shfl_xor_sync(0xffffffffu, sum2, 2);
            float mu = sum * (1.0f / DD);
            float var = sum2 * (1.0f / DD) - mu * mu;
            float rstd = rsqrtf(var + 1e-5f);
#pragma unroll
            for (int j = 0; j < 16; j++) {
                int col = j * 8 + lc * 2;
                float2 hv = *(const float2*)&g_h[(size_t)row * DD + col];
                float y0 = fmaf(of[j][2 * m],     s, hv.x);
                float y1 = fmaf(of[j][2 * m + 1], s, hv.y);
                float2 o;
                o.x = (y0 - mu) * rstd * sg[col]     + sb[col];
                o.y = (y1 - mu) * rstd * sg[col + 1] + sb[col + 1];
                *(float2*)&out[(size_t)row * DD + col] = o;
            }
        }
    }
}

// ---------------- launch ----------------
extern "C" void kernel_launch(void* const* d_in, const int* in_sizes, int n_in,
                              void* d_out, int out_size) {
    const float* x        = (const float*)d_in[0];
    const int*   adj      = (const int*)d_in[1];
    const float* Wgat     = (const float*)d_in[2];
    const float* att_src  = (const float*)d_in[3];
    const float* att_dst  = (const float*)d_in[4];
    const float* bias_gat = (const float*)d_in[5];
    const float* Wq       = (const float*)d_in[6];
    const float* Wk       = (const float*)d_in[7];
    const float* Wpro     = (const float*)d_in[8];
    const float* lng      = (const float*)d_in[9];
    const float* lnb      = (const float*)d_in[10];
    float* out = (float*)d_out;

    k_gemm1<<<NN / 64, 256>>>(x, Wgat, att_src, att_dst);
    {
        int warps = (ETOT + 1) / 2;
        k_edgeacc<<<(warps * 32 + 255) / 256, 256>>>(adj);
    }
    k_gemm2qk<<<NN / 64, 256>>>(bias_gat, Wpro, Wq, Wk);
    k_attnF<<<NN / 64, 256>>>(lng, lnb, out);
}